// round 1
// baseline (speedup 1.0000x reference)
#include <cuda_runtime.h>

#define BB 32
#define NN 128
#define NIN 16
#define MHID 64
#define MOUT 64
#define NHID 64
#define NOUT 16
#define KT 4
#define EDGES (NN * (NN - 1))

// Scratch for per-node first-layer projections (no cudaMalloc allowed).
__device__ float g_U[BB * NN * KT * MHID];  // sender proj
__device__ float g_V[BB * NN * KT * MHID];  // receiver proj (+ b1 folded in)

// ---------------------------------------------------------------------------
// Kernel 1: u[b,n,k,h] = x[b,n,:] @ W1[k][0:16,:]
//           v[b,n,k,h] = x[b,n,:] @ W1[k][16:32,:] + b1[k]
// ---------------------------------------------------------------------------
__global__ __launch_bounds__(256) void uv_kernel(
    const float* __restrict__ inp,   // [B, NIN, N]
    const float* __restrict__ W1,    // [K, 2*NIN, MHID]
    const float* __restrict__ b1)    // [K, MHID]
{
    const int n = blockIdx.x, b = blockIdx.y;
    const int t = threadIdx.x;
    const int k = t >> 6, h = t & 63;

    __shared__ float xs[NIN];
    if (t < NIN) xs[t] = inp[(b * NIN + t) * NN + n];
    __syncthreads();

    const float* w = W1 + k * (2 * NIN) * MHID;
    float u = 0.f;
    float v = b1[k * MHID + h];
#pragma unroll
    for (int f = 0; f < NIN; f++) {
        u = fmaf(xs[f], w[f * MHID + h], u);
        v = fmaf(xs[f], w[(NIN + f) * MHID + h], v);
    }
    const int base = ((b * NN + n) * KT + k) * MHID + h;
    g_U[base] = u;
    g_V[base] = v;
}

// ---------------------------------------------------------------------------
// Kernel 2: one CTA per (b, receiver i).
//  for k in 0..3:
//    h1[j',h] = relu(u[b, j(j'), k, h] + v[b, i, k, h])         (127 x 64)
//    o[j',m]  = relu(h1 @ W2[k] + b2[k])                        (127 x 64)
//    agg[m]  += sum_j' rel_types[b, i*127+j', k] * o[j',m]
//  then node MLP: relu(relu([x_i, agg]@Wo1+bo1)@Wo2+bo2)@Wo3+bo3
// ---------------------------------------------------------------------------
__global__ __launch_bounds__(256) void decoder_kernel(
    const float* __restrict__ inp,       // [B, NIN, N]
    const float* __restrict__ rel_types, // [B, E, K]
    const float* __restrict__ W2,        // [K, MHID, MOUT]
    const float* __restrict__ b2,        // [K, MOUT]
    const float* __restrict__ Wo1,       // [NIN+MOUT, NHID]
    const float* __restrict__ bo1,
    const float* __restrict__ Wo2,       // [NHID, NHID]
    const float* __restrict__ bo2,
    const float* __restrict__ Wo3,       // [NHID, NOUT]
    const float* __restrict__ bo3,
    float* __restrict__ out)             // [B, NOUT, N]
{
    const int i = blockIdx.x, b = blockIdx.y;
    const int t = threadIdx.x;
    const int tm = t >> 4;      // 0..15 : row group
    const int tn = t & 15;      // 0..15 : col group (4 cols each)

    __shared__ float vs[KT][MHID];          // v[b,i,k,:]
    __shared__ float b2s[KT][MOUT];
    __shared__ float rts[NN][KT];           // rel_types rows for receiver i (row 127 = 0)
    __shared__ float h1s[64][65];           // padded to kill bank conflicts
    __shared__ __align__(16) float W2s[64][64];
    __shared__ float aggs[16][MOUT];
    __shared__ float augs[NIN + MOUT];
    __shared__ float hbuf[NHID];
    __shared__ float h2s[NHID];

    // --- stage per-(b,i) constants ---
    vs[t >> 6][t & 63]  = g_V[((b * NN + i) * KT) * MHID + t];  // 256 = 4*64
    b2s[t >> 6][t & 63] = b2[t];
    {
        const float* rtp = rel_types + (size_t)(b * EDGES + i * (NN - 1)) * KT;
        for (int idx = t; idx < (NN - 1) * KT; idx += 256)
            rts[idx >> 2][idx & 3] = rtp[idx];
        if (t < KT) rts[NN - 1][t] = 0.f;   // pad row contributes nothing
    }

    float aggv[4] = {0.f, 0.f, 0.f, 0.f};

    for (int k = 0; k < KT; k++) {
        __syncthreads();  // prior reads of W2s/h1s done (covers initial staging too)
        // stage W2[k] : [h][m]
        for (int idx = t; idx < 64 * 64; idx += 256)
            (&W2s[0][0])[idx] = W2[k * 64 * 64 + idx];

        for (int jt = 0; jt < 2; jt++) {
            if (jt == 1) __syncthreads();   // previous tile's GEMM done reading h1s
            // fill h1 tile: rows jt*64 .. jt*64+63 (global row 127 zeroed)
            for (int idx = t; idx < 64 * 64; idx += 256) {
                const int row = idx >> 6, h = idx & 63;
                const int jg = jt * 64 + row;
                float val = 0.f;
                if (jg < NN - 1) {
                    const int j = jg + (jg >= i);
                    val = g_U[((b * NN + j) * KT + k) * MHID + h] + vs[k][h];
                    val = fmaxf(val, 0.f);
                }
                h1s[row][h] = val;
            }
            __syncthreads();

            // 64x64x64 GEMM, 4x4 per thread
            float acc[4][4];
#pragma unroll
            for (int r = 0; r < 4; r++)
#pragma unroll
                for (int c = 0; c < 4; c++) acc[r][c] = 0.f;

#pragma unroll 8
            for (int kk = 0; kk < 64; kk++) {
                const float a0 = h1s[tm][kk];
                const float a1 = h1s[tm + 16][kk];
                const float a2 = h1s[tm + 32][kk];
                const float a3 = h1s[tm + 48][kk];
                const float4 bv = *(const float4*)&W2s[kk][tn * 4];
                acc[0][0] = fmaf(a0, bv.x, acc[0][0]);
                acc[0][1] = fmaf(a0, bv.y, acc[0][1]);
                acc[0][2] = fmaf(a0, bv.z, acc[0][2]);
                acc[0][3] = fmaf(a0, bv.w, acc[0][3]);
                acc[1][0] = fmaf(a1, bv.x, acc[1][0]);
                acc[1][1] = fmaf(a1, bv.y, acc[1][1]);
                acc[1][2] = fmaf(a1, bv.z, acc[1][2]);
                acc[1][3] = fmaf(a1, bv.w, acc[1][3]);
                acc[2][0] = fmaf(a2, bv.x, acc[2][0]);
                acc[2][1] = fmaf(a2, bv.y, acc[2][1]);
                acc[2][2] = fmaf(a2, bv.z, acc[2][2]);
                acc[2][3] = fmaf(a2, bv.w, acc[2][3]);
                acc[3][0] = fmaf(a3, bv.x, acc[3][0]);
                acc[3][1] = fmaf(a3, bv.y, acc[3][1]);
                acc[3][2] = fmaf(a3, bv.z, acc[3][2]);
                acc[3][3] = fmaf(a3, bv.w, acc[3][3]);
            }

            // fused epilogue: +b2, relu, * rel_types, accumulate over (j, k)
#pragma unroll
            for (int r = 0; r < 4; r++) {
                const int jg = jt * 64 + r * 16 + tm;
                const float rt = rts[jg][k];
#pragma unroll
                for (int c = 0; c < 4; c++) {
                    const int m = tn * 4 + c;
                    const float val = fmaxf(acc[r][c] + b2s[k][m], 0.f);
                    aggv[c] = fmaf(rt, val, aggv[c]);
                }
            }
        }
    }

    // --- cross-thread reduction of agg over the 16 row groups ---
    __syncthreads();
#pragma unroll
    for (int c = 0; c < 4; c++) aggs[tm][tn * 4 + c] = aggv[c];
    __syncthreads();

    // --- node MLP ---
    if (t < NIN) augs[t] = inp[(b * NIN + t) * NN + i];
    if (t < MOUT) {
        float s = 0.f;
#pragma unroll
        for (int q = 0; q < 16; q++) s += aggs[q][t];
        augs[NIN + t] = s;
    }
    __syncthreads();

    if (t < NHID) {
        float s = bo1[t];
#pragma unroll
        for (int f = 0; f < NIN + MOUT; f++) s = fmaf(augs[f], Wo1[f * NHID + t], s);
        hbuf[t] = fmaxf(s, 0.f);
    }
    __syncthreads();

    if (t < NHID) {
        float s = bo2[t];
#pragma unroll
        for (int f = 0; f < NHID; f++) s = fmaf(hbuf[f], Wo2[f * NHID + t], s);
        h2s[t] = fmaxf(s, 0.f);
    }
    __syncthreads();

    if (t < NOUT) {
        float s = bo3[t];
#pragma unroll
        for (int h = 0; h < NHID; h++) s = fmaf(h2s[h], Wo3[h * NOUT + t], s);
        out[(b * NOUT + t) * NN + i] = s;  // [B, NOUT, N]
    }
}

// ---------------------------------------------------------------------------
extern "C" void kernel_launch(void* const* d_in, const int* in_sizes, int n_in,
                              void* d_out, int out_size)
{
    const float* inp       = (const float*)d_in[0];
    // d_in[1] = rel_rec, d_in[2] = rel_send : structure is implicit, unused
    const float* rel_types = (const float*)d_in[3];
    const float* W1  = (const float*)d_in[4];
    const float* b1  = (const float*)d_in[5];
    const float* W2  = (const float*)d_in[6];
    const float* b2  = (const float*)d_in[7];
    const float* Wo1 = (const float*)d_in[8];
    const float* bo1 = (const float*)d_in[9];
    const float* Wo2 = (const float*)d_in[10];
    const float* bo2 = (const float*)d_in[11];
    const float* Wo3 = (const float*)d_in[12];
    const float* bo3 = (const float*)d_in[13];
    float* out = (float*)d_out;

    dim3 grid(NN, BB);
    uv_kernel<<<grid, 256>>>(inp, W1, b1);
    decoder_kernel<<<grid, 256>>>(inp, rel_types, W2, b2,
                                  Wo1, bo1, Wo2, bo2, Wo3, bo3, out);
}

// round 3
// speedup vs baseline: 1.9360x; 1.9360x over previous
#include <cuda_runtime.h>
#include <cstdint>

#define BB 32
#define NN 128
#define NIN 16
#define MHID 64
#define MOUT 64
#define NHID 64
#define NOUT 16
#define KT 4
#define EDGES (NN * (NN - 1))

// Scratch (no cudaMalloc allowed)
__device__ float g_U[BB * NN * KT * MHID];   // [b][n][k][h] sender proj (tc path)
__device__ float g_U2[BB * KT * MHID * NN];  // [b][k][h][n] sender proj (SIMT path)
__device__ float g_V[BB * NN * KT * MHID];   // [b][n][k][h] receiver proj + b1
__device__ float g_W2T[KT * MOUT * MHID];    // W2 transposed, tf32-rounded (tc path)

// ---------------- helpers ----------------
__device__ __forceinline__ uint32_t smem_u32(const void* p) {
    uint32_t a;
    asm("{ .reg .u64 t; cvta.to.shared.u64 t, %1; cvt.u32.u64 %0, t; }" : "=r"(a) : "l"(p));
    return a;
}
__device__ __forceinline__ uint32_t f2tf32(float x) {
    uint32_t r; asm("cvt.rna.tf32.f32 %0, %1;" : "=r"(r) : "f"(x)); return r;
}
// packed fp32 FMA (Blackwell family, plain sm_100+ feature)
__device__ __forceinline__ void fma2(unsigned long long& d, unsigned long long a,
                                     unsigned long long b) {
    asm("fma.rn.f32x2 %0, %1, %2, %0;" : "+l"(d) : "l"(a), "l"(b));
}
__device__ __forceinline__ unsigned long long splat2(float x) {
    unsigned long long r;
    asm("mov.b64 %0, {%1, %1};" : "=l"(r) : "r"(__float_as_uint(x)));
    return r;
}

#if defined(__CUDA_ARCH_FEAT_SM103_ALL)
__device__ __forceinline__ void mma_tf32_ss(uint32_t d, uint64_t a, uint64_t b,
                                            uint32_t idesc, uint32_t en) {
    asm volatile(
        "{\n\t.reg .pred p;\n\tsetp.ne.u32 p, %4, 0;\n\t"
        "tcgen05.mma.cta_group::1.kind::tf32 [%0], %1, %2, %3, {%5, %5, %5, %5}, p;\n\t}\n"
        :: "r"(d), "l"(a), "l"(b), "r"(idesc), "r"(en), "r"(0u) : "memory");
}
#define MBAR_WAIT_PARITY(addr, ph) do {                                          \
    uint32_t _m = (addr), _p = (ph), _done;                                      \
    asm volatile("{\n\t.reg .pred p;\n\t"                                        \
        "mbarrier.try_wait.parity.acquire.cta.shared::cta.b64 p, [%1], %2;\n\t"  \
        "selp.b32 %0, 1, 0, p;\n\t}" : "=r"(_done) : "r"(_m), "r"(_p) : "memory");\
    if (!_done) {                                                                \
        asm volatile("{\n\t.reg .pred P1;\n\t"                                   \
            "WL_%=:\n\t"                                                         \
            "mbarrier.try_wait.parity.acquire.cta.shared::cta.b64 P1, [%0], %1, 0x989680;\n\t" \
            "@P1 bra.uni WD_%=;\n\tbra.uni WL_%=;\n\tWD_%=:\n\t}"                \
            :: "r"(_m), "r"(_p) : "memory");                                     \
    } } while (0)
#define LDTM_X32(r, addr)                                                        \
    asm volatile("tcgen05.ld.sync.aligned.32x32b.x32.b32 "                       \
        "{%0, %1, %2, %3, %4, %5, %6, %7, %8, %9, %10, %11, %12, %13, %14, %15," \
        " %16, %17, %18, %19, %20, %21, %22, %23, %24, %25, %26, %27, %28, %29, %30, %31}, [%32];" \
        : "=r"((r)[0]),  "=r"((r)[1]),  "=r"((r)[2]),  "=r"((r)[3]),             \
          "=r"((r)[4]),  "=r"((r)[5]),  "=r"((r)[6]),  "=r"((r)[7]),             \
          "=r"((r)[8]),  "=r"((r)[9]),  "=r"((r)[10]), "=r"((r)[11]),            \
          "=r"((r)[12]), "=r"((r)[13]), "=r"((r)[14]), "=r"((r)[15]),            \
          "=r"((r)[16]), "=r"((r)[17]), "=r"((r)[18]), "=r"((r)[19]),            \
          "=r"((r)[20]), "=r"((r)[21]), "=r"((r)[22]), "=r"((r)[23]),            \
          "=r"((r)[24]), "=r"((r)[25]), "=r"((r)[26]), "=r"((r)[27]),            \
          "=r"((r)[28]), "=r"((r)[29]), "=r"((r)[30]), "=r"((r)[31])             \
        : "r"(addr))
#define IDESC_TF32 0x08100910u
#define DESC_BASE ((2ull << 61) | (1ull << 46) | (64ull << 32) | (1ull << 16))
__device__ __forceinline__ uint64_t mk_desc(uint32_t addr) {
    return DESC_BASE | ((uint64_t)(addr >> 4) & 0x3FFF);
}
#endif

// ---------------------------------------------------------------------------
// Prologue: W2T[k][m][kk] = tf32(W2[k][kk][m])   (tc path only; cheap)
// ---------------------------------------------------------------------------
__global__ void w2t_kernel(const float* __restrict__ W2) {
    int idx = blockIdx.x * 256 + threadIdx.x;
    if (idx < KT * MOUT * MHID) {
        int k = idx >> 12, rem = idx & 4095, kk = rem >> 6, m = rem & 63;
        uint32_t v = f2tf32(W2[(k * MHID + kk) * MOUT + m]);
        ((uint32_t*)g_W2T)[(k * MOUT + m) * MHID + kk] = v;
    }
}

// ---------------------------------------------------------------------------
// Kernel 1: per-node first-layer projections (both layouts)
// ---------------------------------------------------------------------------
__global__ __launch_bounds__(256) void uv_kernel(
    const float* __restrict__ inp, const float* __restrict__ W1,
    const float* __restrict__ b1)
{
    const int n = blockIdx.x, b = blockIdx.y;
    const int t = threadIdx.x;
    const int k = t >> 6, h = t & 63;
    __shared__ float xs[NIN];
    if (t < NIN) xs[t] = inp[(b * NIN + t) * NN + n];
    __syncthreads();
    const float* w = W1 + k * (2 * NIN) * MHID;
    float u = 0.f, v = b1[k * MHID + h];
#pragma unroll
    for (int f = 0; f < NIN; f++) {
        u = fmaf(xs[f], w[f * MHID + h], u);
        v = fmaf(xs[f], w[(NIN + f) * MHID + h], v);
    }
    g_U[((b * NN + n) * KT + k) * MHID + h] = u;
    g_U2[((b * KT + k) * MHID + h) * NN + n] = u;
    g_V[((b * NN + n) * KT + k) * MHID + h] = v;
}

// ---------------------------------------------------------------------------
// Kernel 2: decoder. One CTA per (b, receiver i).
//   sm_103a pass: tcgen05 tf32 path.   plain sm_103: packed-fp32 SIMT path.
// ---------------------------------------------------------------------------
__global__ __launch_bounds__(256) void decoder_kernel(
    const float* __restrict__ inp, const float* __restrict__ rel_types,
    const float* __restrict__ W2, const float* __restrict__ b2,
    const float* __restrict__ Wo1, const float* __restrict__ bo1,
    const float* __restrict__ Wo2, const float* __restrict__ bo2,
    const float* __restrict__ Wo3, const float* __restrict__ bo3,
    float* __restrict__ out)
{
    extern __shared__ char dsm[];
    const int i = blockIdx.x, b = blockIdx.y;
    const int t = threadIdx.x;

#if defined(__CUDA_ARCH_FEAT_SM103_ALL)
    // ======================= tcgen05 tf32 path =======================
    __shared__ float rts[NN][KT];
    __shared__ float vs[KT][MHID];
    __shared__ float b2s[KT][MOUT];
    __shared__ float pbuf[64][4];
    __shared__ float augs[NIN + MOUT];
    __shared__ float hbuf[NHID];
    __shared__ float h2s[NHID];
    __shared__ uint32_t tmem_ptr_s;
    __shared__ __align__(8) uint64_t mbar;

    const int wid = t >> 5, lane = t & 31;
    uint32_t dyn = smem_u32(dsm);
    uint32_t Abase = (dyn + 1023) & ~1023u;
    uint32_t Bbase = Abase + 32768;
    char* Aptr = dsm + (Abase - dyn);
    char* Bptr = dsm + (Bbase - dyn);
    uint32_t mbar_addr = smem_u32(&mbar);

    if (t == 0)
        asm volatile("mbarrier.init.shared.b64 [%0], 1;" :: "r"(mbar_addr) : "memory");
    if (wid == 0) {
        asm volatile("tcgen05.alloc.cta_group::1.sync.aligned.shared::cta.b32 [%0], %1;"
                     :: "r"(smem_u32(&tmem_ptr_s)), "r"(64u) : "memory");
        asm volatile("tcgen05.relinquish_alloc_permit.cta_group::1.sync.aligned;");
    }
    vs[t >> 6][t & 63]  = g_V[((b * NN + i) * KT) * MHID + t];
    b2s[t >> 6][t & 63] = b2[t];
    {
        const float* rtp = rel_types + (size_t)(b * EDGES + i * (NN - 1)) * KT;
        for (int idx = t; idx < (NN - 1) * KT; idx += 256)
            rts[idx >> 2][idx & 3] = rtp[idx];
        if (t < KT) rts[NN - 1][t] = 0.f;
    }
    __syncthreads();
    const uint32_t tmem = tmem_ptr_s;

    const int colbase = (wid >> 2) * 32;
    const int jrow = (wid & 3) * 32 + lane;
    float acc[32];
#pragma unroll
    for (int c = 0; c < 32; c++) acc[c] = 0.f;

    for (int k = 0; k < KT; k++) {
        __syncthreads();
        for (int idx = t; idx < 128 * 16; idx += 256) {
            const int r = idx >> 4, c = (idx & 15) * 4;
            uint4 w4 = make_uint4(0u, 0u, 0u, 0u);
            if (r < NN - 1) {
                const int j = r + (r >= i);
                const float4 u = *(const float4*)(g_U + ((b * NN + j) * KT + k) * MHID + c);
                w4.x = f2tf32(fmaxf(u.x + vs[k][c + 0], 0.f));
                w4.y = f2tf32(fmaxf(u.y + vs[k][c + 1], 0.f));
                w4.z = f2tf32(fmaxf(u.z + vs[k][c + 2], 0.f));
                w4.w = f2tf32(fmaxf(u.w + vs[k][c + 3], 0.f));
            }
            uint32_t byte = ((r >> 3) + (c >> 5) * 16) * 1024 + (r & 7) * 128 + (c & 31) * 4;
            byte ^= (byte >> 3) & 0x70;
            *(uint4*)(Aptr + byte) = w4;
        }
        for (int idx = t; idx < 64 * 16; idx += 256) {
            const int n = idx >> 4, c = (idx & 15) * 4;
            uint4 w4 = *(const uint4*)((const uint32_t*)g_W2T + (k * MOUT + n) * MHID + c);
            uint32_t byte = ((n >> 3) + (c >> 5) * 8) * 1024 + (n & 7) * 128 + (c & 31) * 4;
            byte ^= (byte >> 3) & 0x70;
            *(uint4*)(Bptr + byte) = w4;
        }
        __syncthreads();

        if (t == 0) {
            asm volatile("fence.proxy.async.shared::cta;" ::: "memory");
            const uint64_t ad = mk_desc(Abase), bd = mk_desc(Bbase);
#pragma unroll
            for (int s = 0; s < 8; s++) {
                mma_tf32_ss(tmem, ad + ((s >> 2) ? 1024u : 0u) + (s & 3) * 2,
                                  bd + ((s >> 2) ? 512u : 0u) + (s & 3) * 2,
                            IDESC_TF32, (uint32_t)(s > 0));
            }
            asm volatile(
                "tcgen05.commit.cta_group::1.mbarrier::arrive::one.shared::cluster.b64 [%0];"
                :: "r"(mbar_addr) : "memory");
        }
        MBAR_WAIT_PARITY(mbar_addr, k & 1);
        asm volatile("tcgen05.fence::after_thread_sync;" ::: "memory");
        {
            uint32_t d[32];
            LDTM_X32(d, tmem + colbase);
            asm volatile("tcgen05.wait::ld.sync.aligned;" ::: "memory");
            const float rt = rts[jrow][k];
#pragma unroll
            for (int c = 0; c < 32; c++) {
                const float val = fmaxf(__uint_as_float(d[c]) + b2s[k][colbase + c], 0.f);
                acc[c] = fmaf(rt, val, acc[c]);
            }
            asm volatile("tcgen05.fence::before_thread_sync;" ::: "memory");
        }
    }
    __syncthreads();
    if (t == 0)
        asm volatile("mbarrier.inval.shared.b64 [%0];" :: "r"(mbar_addr) : "memory");
    if (wid == 0)
        asm volatile("tcgen05.dealloc.cta_group::1.sync.aligned.b32 %0, %1;"
                     :: "r"(tmem), "r"(64u));

    float* red = (float*)Aptr;  // [64 m][128 j]
#pragma unroll
    for (int c = 0; c < 32; c++) red[(colbase + c) * 128 + jrow] = acc[c];
    __syncthreads();
    {
        const int m = t >> 2, q = t & 3;
        float s = 0.f;
#pragma unroll
        for (int l = 0; l < 32; l++)
            s += red[m * 128 + q * 32 + ((l + lane) & 31)];
        pbuf[m][q] = s;
    }
    __syncthreads();
    if (t < NIN) augs[t] = inp[(b * NIN + t) * NN + i];
    if (t < MOUT) augs[NIN + t] = pbuf[t][0] + pbuf[t][1] + pbuf[t][2] + pbuf[t][3];
    __syncthreads();
    if (t < NHID) {
        float s = bo1[t];
#pragma unroll
        for (int f = 0; f < NIN + MOUT; f++) s = fmaf(augs[f], Wo1[f * NHID + t], s);
        hbuf[t] = fmaxf(s, 0.f);
    }
    __syncthreads();
    if (t < NHID) {
        float s = bo2[t];
#pragma unroll
        for (int f = 0; f < NHID; f++) s = fmaf(hbuf[f], Wo2[f * NHID + t], s);
        h2s[t] = fmaxf(s, 0.f);
    }
    __syncthreads();
    if (t < NOUT) {
        float s = bo3[t];
#pragma unroll
        for (int h = 0; h < NHID; h++) s = fmaf(h2s[h], Wo3[h * NOUT + t], s);
        out[(b * NOUT + t) * NN + i] = s;
    }
#else
    // ================== packed-fp32 SIMT path (f32x2) ==================
    __shared__ float rts[NN][KT];
    __shared__ float vs[KT][MHID];
    __shared__ float b2s[KT][MOUT];
    __shared__ float aggs[16][MOUT];
    __shared__ float augs[NIN + MOUT];
    __shared__ float hbuf[NHID];
    __shared__ float h2s[NHID];

    float* h1T = (float*)dsm;          // [64 kk][128 j]  32 KB
    float* W2s = h1T + 64 * 128;       // [64 kk][64 m]   16 KB

    const int tm = t >> 4;   // 0..15 -> rows 8*tm .. 8*tm+7
    const int tn = t & 15;   // 0..15 -> cols 4*tn .. 4*tn+3

    vs[t >> 6][t & 63]  = g_V[((b * NN + i) * KT) * MHID + t];
    b2s[t >> 6][t & 63] = b2[t];
    {
        const float* rtp = rel_types + (size_t)(b * EDGES + i * (NN - 1)) * KT;
        for (int idx = t; idx < (NN - 1) * KT; idx += 256)
            rts[idx >> 2][idx & 3] = rtp[idx];
        if (t < KT) rts[NN - 1][t] = 0.f;
    }

    float aggv[4] = {0.f, 0.f, 0.f, 0.f};

    for (int k = 0; k < KT; k++) {
        __syncthreads();   // previous GEMM done reading tiles (and staging sync)
        // build h1T[h][jr] = relu(u2[b][k][h][j] + vs[k][h]) ; row 127 zero
        for (int idx = t; idx < MHID * NN; idx += 256) {
            const int h = idx >> 7, jr = idx & 127;
            float val = 0.f;
            if (jr < NN - 1) {
                const int j = jr + (jr >= i);
                val = fmaxf(g_U2[((b * KT + k) * MHID + h) * NN + j] + vs[k][h], 0.f);
            }
            h1T[h * 128 + jr] = val;
        }
        for (int idx = t; idx < MHID * MOUT; idx += 256)
            W2s[idx] = W2[k * MHID * MOUT + idx];
        __syncthreads();

        unsigned long long acc[4][4];
#pragma unroll
        for (int p = 0; p < 4; p++)
#pragma unroll
            for (int c = 0; c < 4; c++) acc[p][c] = 0ull;

#pragma unroll 4
        for (int kk = 0; kk < 64; kk++) {
            const ulonglong2 a01 = *(const ulonglong2*)(h1T + kk * 128 + 8 * tm);
            const ulonglong2 a23 = *(const ulonglong2*)(h1T + kk * 128 + 8 * tm + 4);
            const float4 bv = *(const float4*)(W2s + kk * 64 + 4 * tn);
            const unsigned long long bp0 = splat2(bv.x);
            const unsigned long long bp1 = splat2(bv.y);
            const unsigned long long bp2 = splat2(bv.z);
            const unsigned long long bp3 = splat2(bv.w);
            fma2(acc[0][0], a01.x, bp0); fma2(acc[0][1], a01.x, bp1);
            fma2(acc[0][2], a01.x, bp2); fma2(acc[0][3], a01.x, bp3);
            fma2(acc[1][0], a01.y, bp0); fma2(acc[1][1], a01.y, bp1);
            fma2(acc[1][2], a01.y, bp2); fma2(acc[1][3], a01.y, bp3);
            fma2(acc[2][0], a23.x, bp0); fma2(acc[2][1], a23.x, bp1);
            fma2(acc[2][2], a23.x, bp2); fma2(acc[2][3], a23.x, bp3);
            fma2(acc[3][0], a23.y, bp0); fma2(acc[3][1], a23.y, bp1);
            fma2(acc[3][2], a23.y, bp2); fma2(acc[3][3], a23.y, bp3);
        }

        // epilogue: relu(+b2) * rel_types, accumulate over rows & k
#pragma unroll
        for (int p = 0; p < 4; p++) {
            const float rt0 = rts[8 * tm + 2 * p][k];
            const float rt1 = rts[8 * tm + 2 * p + 1][k];
#pragma unroll
            for (int c = 0; c < 4; c++) {
                const float bb = b2s[k][4 * tn + c];
                const float lo = __uint_as_float((uint32_t)acc[p][c]);
                const float hi = __uint_as_float((uint32_t)(acc[p][c] >> 32));
                aggv[c] = fmaf(rt0, fmaxf(lo + bb, 0.f), aggv[c]);
                aggv[c] = fmaf(rt1, fmaxf(hi + bb, 0.f), aggv[c]);
            }
        }
    }

    __syncthreads();
#pragma unroll
    for (int c = 0; c < 4; c++) aggs[tm][4 * tn + c] = aggv[c];
    __syncthreads();

    if (t < NIN) augs[t] = inp[(b * NIN + t) * NN + i];
    if (t < MOUT) {
        float s = 0.f;
#pragma unroll
        for (int q = 0; q < 16; q++) s += aggs[q][t];
        augs[NIN + t] = s;
    }
    __syncthreads();
    if (t < NHID) {
        float s = bo1[t];
#pragma unroll
        for (int f = 0; f < NIN + MOUT; f++) s = fmaf(augs[f], Wo1[f * NHID + t], s);
        hbuf[t] = fmaxf(s, 0.f);
    }
    __syncthreads();
    if (t < NHID) {
        float s = bo2[t];
#pragma unroll
        for (int f = 0; f < NHID; f++) s = fmaf(hbuf[f], Wo2[f * NHID + t], s);
        h2s[t] = fmaxf(s, 0.f);
    }
    __syncthreads();
    if (t < NOUT) {
        float s = bo3[t];
#pragma unroll
        for (int h = 0; h < NHID; h++) s = fmaf(h2s[h], Wo3[h * NOUT + t], s);
        out[(b * NOUT + t) * NN + i] = s;
    }
#endif
}

// ---------------------------------------------------------------------------
extern "C" void kernel_launch(void* const* d_in, const int* in_sizes, int n_in,
                              void* d_out, int out_size)
{
    const float* inp       = (const float*)d_in[0];
    const float* rel_types = (const float*)d_in[3];
    const float* W1  = (const float*)d_in[4];
    const float* b1  = (const float*)d_in[5];
    const float* W2  = (const float*)d_in[6];
    const float* b2  = (const float*)d_in[7];
    const float* Wo1 = (const float*)d_in[8];
    const float* bo1 = (const float*)d_in[9];
    const float* Wo2 = (const float*)d_in[10];
    const float* bo2 = (const float*)d_in[11];
    const float* Wo3 = (const float*)d_in[12];
    const float* bo3 = (const float*)d_in[13];
    float* out = (float*)d_out;

    // idempotent; ignore result (already set by the pre-capture correctness call)
    (void)cudaFuncSetAttribute(decoder_kernel,
                               cudaFuncAttributeMaxDynamicSharedMemorySize, 50176);

    dim3 grid(NN, BB);
    w2t_kernel<<<64, 256>>>(W2);
    uv_kernel<<<grid, 256>>>(inp, W1, b1);
    decoder_kernel<<<grid, 256, 50176>>>(inp, rel_types, W2, b2,
                                         Wo1, bo1, Wo2, bo2, Wo3, bo3, out);
}

// round 4
// speedup vs baseline: 2.1184x; 1.0943x over previous
#include <cuda_runtime.h>
#include <cstdint>

#define BB 32
#define NN 128
#define NIN 16
#define MHID 64
#define MOUT 64
#define NHID 64
#define NOUT 16
#define KT 4
#define EDGES (NN * (NN - 1))

// Scratch (no cudaMalloc allowed)
__device__ float g_U[BB * NN * KT * MHID];   // [b][n][k][h] sender proj
__device__ float g_V[BB * NN * KT * MHID];   // [b][n][k][h] receiver proj + b1
__device__ float g_W2T[KT * MOUT * MHID];    // W2 transposed [k][m][kk], tf32-rounded

// ---------------- helpers ----------------
__device__ __forceinline__ uint32_t smem_u32(const void* p) {
    uint32_t a;
    asm("{ .reg .u64 t; cvta.to.shared.u64 t, %1; cvt.u32.u64 %0, t; }" : "=r"(a) : "l"(p));
    return a;
}
__device__ __forceinline__ uint32_t f2tf32(float x) {
    uint32_t r; asm("cvt.rna.tf32.f32 %0, %1;" : "=r"(r) : "f"(x)); return r;
}

#if defined(__CUDA_ARCH_FEAT_SM103_ALL)
__device__ __forceinline__ void mma_tf32_ss(uint32_t d, uint64_t a, uint64_t b,
                                            uint32_t idesc, uint32_t en) {
    asm volatile(
        "{\n\t.reg .pred p;\n\tsetp.ne.u32 p, %4, 0;\n\t"
        "tcgen05.mma.cta_group::1.kind::tf32 [%0], %1, %2, %3, {%5, %5, %5, %5}, p;\n\t}\n"
        :: "r"(d), "l"(a), "l"(b), "r"(idesc), "r"(en), "r"(0u) : "memory");
}
#define MBAR_WAIT_PARITY(addr, ph) do {                                          \
    uint32_t _m = (addr), _p = (ph), _done;                                      \
    asm volatile("{\n\t.reg .pred p;\n\t"                                        \
        "mbarrier.try_wait.parity.acquire.cta.shared::cta.b64 p, [%1], %2;\n\t"  \
        "selp.b32 %0, 1, 0, p;\n\t}" : "=r"(_done) : "r"(_m), "r"(_p) : "memory");\
    if (!_done) {                                                                \
        asm volatile("{\n\t.reg .pred P1;\n\t"                                   \
            "WL_%=:\n\t"                                                         \
            "mbarrier.try_wait.parity.acquire.cta.shared::cta.b64 P1, [%0], %1, 0x989680;\n\t" \
            "@P1 bra.uni WD_%=;\n\tbra.uni WL_%=;\n\tWD_%=:\n\t}"                \
            :: "r"(_m), "r"(_p) : "memory");                                     \
    } } while (0)
#define LDTM_X16(r, addr)                                                        \
    asm volatile("tcgen05.ld.sync.aligned.32x32b.x16.b32 "                       \
        "{%0, %1, %2, %3, %4, %5, %6, %7, %8, %9, %10, %11, %12, %13, %14, %15}, [%16];" \
        : "=r"((r)[0]),  "=r"((r)[1]),  "=r"((r)[2]),  "=r"((r)[3]),             \
          "=r"((r)[4]),  "=r"((r)[5]),  "=r"((r)[6]),  "=r"((r)[7]),             \
          "=r"((r)[8]),  "=r"((r)[9]),  "=r"((r)[10]), "=r"((r)[11]),            \
          "=r"((r)[12]), "=r"((r)[13]), "=r"((r)[14]), "=r"((r)[15])             \
        : "r"(addr))
#define IDESC_TF32 0x08100910u
#define DESC_BASE ((2ull << 61) | (1ull << 46) | (64ull << 32) | (1ull << 16))
__device__ __forceinline__ uint64_t mk_desc(uint32_t addr) {
    return DESC_BASE | ((uint64_t)(addr >> 4) & 0x3FFF);
}
#endif

// dynamic smem layout offsets (from 1024-aligned base)
#define OFF_B    0        // 4 x 16384 = 65536 (W2T tiles, SW128) [tc path]
#define OFF_A0   65536    // 32768
#define OFF_A1   98304    // 32768
#define OFF_WO1  131072   // 80*64*4 = 20480
#define OFF_WO2  151552   // 64*64*4 = 16384
#define OFF_WO3  167936   // 64*16*4 = 4096
#define OFF_BO   172032   // bo1[64], bo2[64], bo3[16]
#define DYN_BYTES 174080

// ---------------------------------------------------------------------------
__global__ void w2t_kernel(const float* __restrict__ W2) {
    int idx = blockIdx.x * 256 + threadIdx.x;
    if (idx < KT * MOUT * MHID) {
        int k = idx >> 12, rem = idx & 4095, kk = rem >> 6, m = rem & 63;
        uint32_t v = f2tf32(W2[(k * MHID + kk) * MOUT + m]);
        ((uint32_t*)g_W2T)[(k * MOUT + m) * MHID + kk] = v;
    }
}

// ---------------------------------------------------------------------------
__global__ __launch_bounds__(256) void uv_kernel(
    const float* __restrict__ inp, const float* __restrict__ W1,
    const float* __restrict__ b1)
{
    const int n = blockIdx.x, b = blockIdx.y;
    const int t = threadIdx.x;
    const int k = t >> 6, h = t & 63;
    __shared__ float xs[NIN];
    if (t < NIN) xs[t] = inp[(b * NIN + t) * NN + n];
    __syncthreads();
    const float* w = W1 + k * (2 * NIN) * MHID;
    float u = 0.f, v = b1[k * MHID + h];
#pragma unroll
    for (int f = 0; f < NIN; f++) {
        u = fmaf(xs[f], w[f * MHID + h], u);
        v = fmaf(xs[f], w[(NIN + f) * MHID + h], v);
    }
    g_U[((b * NN + n) * KT + k) * MHID + h] = u;
    g_V[((b * NN + n) * KT + k) * MHID + h] = v;
}

// ---------------------------------------------------------------------------
// Persistent decoder: grid = 148, 512 threads, 1 CTA/SM.
// ---------------------------------------------------------------------------
__global__ __launch_bounds__(512, 1) void decoder_kernel(
    const float* __restrict__ inp, const float* __restrict__ rel_types,
    const float* __restrict__ W2, const float* __restrict__ b2,
    const float* __restrict__ Wo1, const float* __restrict__ bo1,
    const float* __restrict__ Wo2, const float* __restrict__ bo2,
    const float* __restrict__ Wo3, const float* __restrict__ bo3,
    float* __restrict__ out)
{
    extern __shared__ char dsm[];
    __shared__ float rts[NN][KT];
    __shared__ float vs[KT][MHID];
    __shared__ float b2s[KT][MOUT];
    __shared__ float pbuf[64][8];
    __shared__ float augs[NIN + MOUT];
    __shared__ float hbuf[NHID];
    __shared__ float h2s[NHID];
    __shared__ uint32_t tmem_ptr_s;
    __shared__ __align__(8) uint64_t mbar[2];

    const int t = threadIdx.x;
    const int wid = t >> 5, lane = t & 31;

    const uint32_t dyn = smem_u32(dsm);
    const uint32_t base = (dyn + 1023) & ~1023u;
    char* P = dsm + (base - dyn);
    float* sWo1 = (float*)(P + OFF_WO1);
    float* sWo2 = (float*)(P + OFF_WO2);
    float* sWo3 = (float*)(P + OFF_WO3);
    float* sbo  = (float*)(P + OFF_BO);

    // ---- one-time staging: node-MLP weights + b2 ----
    for (int idx = t; idx < 80 * 64; idx += 512) sWo1[idx] = Wo1[idx];
    for (int idx = t; idx < 64 * 64; idx += 512) sWo2[idx] = Wo2[idx];
    for (int idx = t; idx < 64 * 16; idx += 512) sWo3[idx] = Wo3[idx];
    if (t < 64) sbo[t] = bo1[t];
    if (t < 64) sbo[64 + t] = bo2[t];
    if (t < 16) sbo[128 + t] = bo3[t];
    if (t < 256) b2s[t >> 6][t & 63] = b2[t];

#if defined(__CUDA_ARCH_FEAT_SM103_ALL)
    // =================== tcgen05 tf32 persistent path ===================
    char* Aptr[2] = { P + OFF_A0, P + OFF_A1 };
    const uint32_t mb[2] = { smem_u32(&mbar[0]), smem_u32(&mbar[1]) };

    // stage all 4 B tiles (W2T, SW128 blocked-atom) once
    for (int idx = t; idx < KT * 64 * 16; idx += 512) {
        const int k = idx >> 10, n = (idx >> 4) & 63, c = (idx & 15) * 4;
        uint4 w4 = *(const uint4*)((const uint32_t*)g_W2T + (k * MOUT + n) * MHID + c);
        uint32_t byte = ((n >> 3) + (c >> 5) * 8) * 1024 + (n & 7) * 128 + (c & 31) * 4;
        byte ^= (byte >> 3) & 0x70;
        *(uint4*)(P + OFF_B + k * 16384 + byte) = w4;
    }
    if (t == 0) {
        asm volatile("mbarrier.init.shared.b64 [%0], 1;" :: "r"(mb[0]) : "memory");
        asm volatile("mbarrier.init.shared.b64 [%0], 1;" :: "r"(mb[1]) : "memory");
    }
    if (wid == 0) {
        asm volatile("tcgen05.alloc.cta_group::1.sync.aligned.shared::cta.b32 [%0], %1;"
                     :: "r"(smem_u32(&tmem_ptr_s)), "r"(128u) : "memory");
        asm volatile("tcgen05.relinquish_alloc_permit.cta_group::1.sync.aligned;");
    }
    __syncthreads();
    const uint32_t tmem = tmem_ptr_s;

    const int colbase = (wid >> 2) * 16;      // {0,16,32,48}
    const int jrow = (wid & 3) * 32 + lane;   // 0..127
    int ph[2] = {0, 0};

    for (int tile = blockIdx.x; tile < BB * NN; tile += gridDim.x) {
        const int b = tile >> 7, i = tile & 127;
        __syncthreads();  // previous tile fully done before restaging
        if (t < 256) vs[t >> 6][t & 63] = g_V[((b * NN + i) * KT) * MHID + t];
        {
            const float* rtp = rel_types + (size_t)(b * EDGES + i * (NN - 1)) * KT;
            for (int idx = t; idx < (NN - 1) * KT; idx += 512)
                rts[idx >> 2][idx & 3] = rtp[idx];
            if (t < KT) rts[NN - 1][t] = 0.f;
        }
        __syncthreads();

        // prologue: build + issue k=0,1
#pragma unroll
        for (int k = 0; k < 2; k++) {
            for (int idx = t; idx < 128 * 16; idx += 512) {
                const int r = idx >> 4, c = (idx & 15) * 4;
                uint4 w4 = make_uint4(0u, 0u, 0u, 0u);
                if (r < NN - 1) {
                    const int j = r + (r >= i);
                    const float4 u = *(const float4*)(g_U + ((b * NN + j) * KT + k) * MHID + c);
                    w4.x = f2tf32(fmaxf(u.x + vs[k][c + 0], 0.f));
                    w4.y = f2tf32(fmaxf(u.y + vs[k][c + 1], 0.f));
                    w4.z = f2tf32(fmaxf(u.z + vs[k][c + 2], 0.f));
                    w4.w = f2tf32(fmaxf(u.w + vs[k][c + 3], 0.f));
                }
                uint32_t byte = ((r >> 3) + (c >> 5) * 16) * 1024 + (r & 7) * 128 + (c & 31) * 4;
                byte ^= (byte >> 3) & 0x70;
                *(uint4*)(Aptr[k] + byte) = w4;
            }
            __syncthreads();
            if (t == 0) {
                asm volatile("fence.proxy.async.shared::cta;" ::: "memory");
                const uint64_t ad = mk_desc(base + OFF_A0 + k * 32768);
                const uint64_t bd = mk_desc(base + OFF_B + k * 16384);
#pragma unroll
                for (int s = 0; s < 8; s++)
                    mma_tf32_ss(tmem + k * 64,
                                ad + ((s >> 2) ? 1024u : 0u) + (s & 3) * 2,
                                bd + ((s >> 2) ? 512u : 0u) + (s & 3) * 2,
                                IDESC_TF32, (uint32_t)(s > 0));
                asm volatile(
                    "tcgen05.commit.cta_group::1.mbarrier::arrive::one.shared::cluster.b64 [%0];"
                    :: "r"(mb[k]) : "memory");
            }
        }

        float acc[16];
#pragma unroll
        for (int c = 0; c < 16; c++) acc[c] = 0.f;

        for (int k = 0; k < KT; k++) {
            const int q = k & 1;
            MBAR_WAIT_PARITY(mb[q], ph[q]);
            ph[q] ^= 1;
            asm volatile("tcgen05.fence::after_thread_sync;" ::: "memory");
            {
                uint32_t d[16];
                LDTM_X16(d, tmem + q * 64 + colbase);
                asm volatile("tcgen05.wait::ld.sync.aligned;" ::: "memory");
                const float rt = rts[jrow][k];
#pragma unroll
                for (int c = 0; c < 16; c++) {
                    const float val = fmaxf(__uint_as_float(d[c]) + b2s[k][colbase + c], 0.f);
                    acc[c] = fmaf(rt, val, acc[c]);
                }
            }
            asm volatile("tcgen05.fence::before_thread_sync;" ::: "memory");
            if (k < 2) {  // build & issue k+2 into the buffer/TMEM bank just freed
                const int kk2 = k + 2;
                for (int idx = t; idx < 128 * 16; idx += 512) {
                    const int r = idx >> 4, c = (idx & 15) * 4;
                    uint4 w4 = make_uint4(0u, 0u, 0u, 0u);
                    if (r < NN - 1) {
                        const int j = r + (r >= i);
                        const float4 u = *(const float4*)(g_U + ((b * NN + j) * KT + kk2) * MHID + c);
                        w4.x = f2tf32(fmaxf(u.x + vs[kk2][c + 0], 0.f));
                        w4.y = f2tf32(fmaxf(u.y + vs[kk2][c + 1], 0.f));
                        w4.z = f2tf32(fmaxf(u.z + vs[kk2][c + 2], 0.f));
                        w4.w = f2tf32(fmaxf(u.w + vs[kk2][c + 3], 0.f));
                    }
                    uint32_t byte = ((r >> 3) + (c >> 5) * 16) * 1024 + (r & 7) * 128 + (c & 31) * 4;
                    byte ^= (byte >> 3) & 0x70;
                    *(uint4*)(Aptr[q] + byte) = w4;
                }
            }
            __syncthreads();
            if (t == 0 && k < 2) {
                const int kk2 = k + 2;
                asm volatile("fence.proxy.async.shared::cta;" ::: "memory");
                const uint64_t ad = mk_desc(base + OFF_A0 + q * 32768);
                const uint64_t bd = mk_desc(base + OFF_B + kk2 * 16384);
#pragma unroll
                for (int s = 0; s < 8; s++)
                    mma_tf32_ss(tmem + q * 64,
                                ad + ((s >> 2) ? 1024u : 0u) + (s & 3) * 2,
                                bd + ((s >> 2) ? 512u : 0u) + (s & 3) * 2,
                                IDESC_TF32, (uint32_t)(s > 0));
                asm volatile(
                    "tcgen05.commit.cta_group::1.mbarrier::arrive::one.shared::cluster.b64 [%0];"
                    :: "r"(mb[q]) : "memory");
            }
        }

        // ---- j-reduction (A buffers free: last MMA completed & waited) ----
        float* red = (float*)(P + OFF_A0);  // [64 m][stride 132]
#pragma unroll
        for (int c = 0; c < 16; c++) red[(colbase + c) * 132 + jrow] = acc[c];
        __syncthreads();
        {
            const int m = t >> 3, qq = t & 7;
            float s = 0.f;
#pragma unroll
            for (int l = 0; l < 16; l++) s += red[m * 132 + qq * 16 + l];
            pbuf[m][qq] = s;
        }
        __syncthreads();

        // ---- node MLP ----
        if (t < NIN) augs[t] = inp[(b * NIN + t) * NN + i];
        if (t < MOUT) {
            float s = 0.f;
#pragma unroll
            for (int qq = 0; qq < 8; qq++) s += pbuf[t][qq];
            augs[NIN + t] = s;
        }
        __syncthreads();
        if (t < NHID) {
            float s = sbo[t];
#pragma unroll
            for (int f = 0; f < NIN + MOUT; f++) s = fmaf(augs[f], sWo1[f * NHID + t], s);
            hbuf[t] = fmaxf(s, 0.f);
        }
        __syncthreads();
        if (t < NHID) {
            float s = sbo[64 + t];
#pragma unroll
            for (int f = 0; f < NHID; f++) s = fmaf(hbuf[f], sWo2[f * NHID + t], s);
            h2s[t] = fmaxf(s, 0.f);
        }
        __syncthreads();
        if (t < NOUT) {
            float s = sbo[128 + t];
#pragma unroll
            for (int h = 0; h < NHID; h++) s = fmaf(h2s[h], sWo3[h * NOUT + t], s);
            out[(b * NOUT + t) * NN + i] = s;
        }
    }

    __syncthreads();
    if (t == 0) {
        asm volatile("mbarrier.inval.shared.b64 [%0];" :: "r"(mb[0]) : "memory");
        asm volatile("mbarrier.inval.shared.b64 [%0];" :: "r"(mb[1]) : "memory");
    }
    if (wid == 0)
        asm volatile("tcgen05.dealloc.cta_group::1.sync.aligned.b32 %0, %1;"
                     :: "r"(tmem), "r"(128u));
#else
    // ============ SIMT fallback (compile-only for plain sm_103) ============
    float* h1  = (float*)P;                 // [128][68]
    float* W2s = (float*)(P + 128 * 68 * 4);

    for (int tile = blockIdx.x; tile < BB * NN; tile += gridDim.x) {
        const int b = tile >> 7, i = tile & 127;
        __syncthreads();
        if (t < 256) vs[t >> 6][t & 63] = g_V[((b * NN + i) * KT) * MHID + t];
        {
            const float* rtp = rel_types + (size_t)(b * EDGES + i * (NN - 1)) * KT;
            for (int idx = t; idx < (NN - 1) * KT; idx += 512)
                rts[idx >> 2][idx & 3] = rtp[idx];
            if (t < KT) rts[NN - 1][t] = 0.f;
        }

        const int r = t >> 2, cq = (t & 3) * 16;
        float aggv[16];
#pragma unroll
        for (int c = 0; c < 16; c++) aggv[c] = 0.f;

        for (int k = 0; k < KT; k++) {
            __syncthreads();
            for (int idx = t; idx < 128 * 64; idx += 512) {
                const int rr = idx >> 6, h = idx & 63;
                float val = 0.f;
                if (rr < NN - 1) {
                    const int j = rr + (rr >= i);
                    val = fmaxf(g_U[((b * NN + j) * KT + k) * MHID + h] + vs[k][h], 0.f);
                }
                h1[rr * 68 + h] = val;
            }
            for (int idx = t; idx < 64 * 64; idx += 512)
                W2s[idx] = W2[k * 64 * 64 + idx];
            __syncthreads();

            float acc[16];
#pragma unroll
            for (int c = 0; c < 16; c++) acc[c] = 0.f;
            for (int kk = 0; kk < 64; kk++) {
                const float a = h1[r * 68 + kk];
#pragma unroll
                for (int c = 0; c < 16; c++)
                    acc[c] = fmaf(a, W2s[kk * 64 + cq + c], acc[c]);
            }
            const float rt = rts[r][k];
#pragma unroll
            for (int c = 0; c < 16; c++)
                aggv[c] = fmaf(rt, fmaxf(acc[c] + b2s[k][cq + c], 0.f), aggv[c]);
        }

        __syncthreads();
        float* red = (float*)P;  // [64 m][stride 132]
#pragma unroll
        for (int c = 0; c < 16; c++) red[(cq + c) * 132 + r] = aggv[c];
        __syncthreads();
        {
            const int m = t >> 3, qq = t & 7;
            float s = 0.f;
#pragma unroll
            for (int l = 0; l < 16; l++) s += red[m * 132 + qq * 16 + l];
            pbuf[m][qq] = s;
        }
        __syncthreads();
        if (t < NIN) augs[t] = inp[(b * NIN + t) * NN + i];
        if (t < MOUT) {
            float s = 0.f;
#pragma unroll
            for (int qq = 0; qq < 8; qq++) s += pbuf[t][qq];
            augs[NIN + t] = s;
        }
        __syncthreads();
        if (t < NHID) {
            float s = sbo[t];
#pragma unroll
            for (int f = 0; f < NIN + MOUT; f++) s = fmaf(augs[f], sWo1[f * NHID + t], s);
            hbuf[t] = fmaxf(s, 0.f);
        }
        __syncthreads();
        if (t < NHID) {
            float s = sbo[64 + t];
#pragma unroll
            for (int f = 0; f < NHID; f++) s = fmaf(hbuf[f], sWo2[f * NHID + t], s);
            h2s[t] = fmaxf(s, 0.f);
        }
        __syncthreads();
        if (t < NOUT) {
            float s = sbo[128 + t];
#pragma unroll
            for (int h = 0; h < NHID; h++) s = fmaf(h2s[h], sWo3[h * NOUT + t], s);
            out[(b * NOUT + t) * NN + i] = s;
        }
    }
#endif
}

// ---------------------------------------------------------------------------
extern "C" void kernel_launch(void* const* d_in, const int* in_sizes, int n_in,
                              void* d_out, int out_size)
{
    const float* inp       = (const float*)d_in[0];
    const float* rel_types = (const float*)d_in[3];
    const float* W1  = (const float*)d_in[4];
    const float* b1  = (const float*)d_in[5];
    const float* W2  = (const float*)d_in[6];
    const float* b2  = (const float*)d_in[7];
    const float* Wo1 = (const float*)d_in[8];
    const float* bo1 = (const float*)d_in[9];
    const float* Wo2 = (const float*)d_in[10];
    const float* bo2 = (const float*)d_in[11];
    const float* Wo3 = (const float*)d_in[12];
    const float* bo3 = (const float*)d_in[13];
    float* out = (float*)d_out;

    (void)cudaFuncSetAttribute(decoder_kernel,
                               cudaFuncAttributeMaxDynamicSharedMemorySize, DYN_BYTES);

    w2t_kernel<<<64, 256>>>(W2);
    uv_kernel<<<dim3(NN, BB), 256>>>(inp, W1, b1);
    decoder_kernel<<<148, 512, DYN_BYTES>>>(inp, rel_types, W2, b2,
                                            Wo1, bo1, Wo2, bo2, Wo3, bo3, out);
}

// round 5
// speedup vs baseline: 2.3451x; 1.1070x over previous
#include <cuda_runtime.h>
#include <cstdint>

#define BB 32
#define NN 128
#define NIN 16
#define MHID 64
#define MOUT 64
#define NHID 64
#define NOUT 16
#define KT 4
#define EDGES (NN * (NN - 1))

// Scratch (no cudaMalloc allowed)
__device__ float g_U[BB * NN * KT * MHID];   // [b][n][k][h] sender proj
__device__ float g_V[BB * NN * KT * MHID];   // [b][n][k][h] receiver proj + b1
__device__ float g_W2T[KT * MOUT * MHID];    // W2 transposed [k][m][kk], tf32-rounded
__device__ float g_AGG[BB * NN * MOUT];      // aggregated messages per node

// ---------------- helpers ----------------
__device__ __forceinline__ uint32_t smem_u32(const void* p) {
    uint32_t a;
    asm("{ .reg .u64 t; cvta.to.shared.u64 t, %1; cvt.u32.u64 %0, t; }" : "=r"(a) : "l"(p));
    return a;
}
__device__ __forceinline__ uint32_t f2tf32(float x) {
    uint32_t r; asm("cvt.rna.tf32.f32 %0, %1;" : "=r"(r) : "f"(x)); return r;
}

#if defined(__CUDA_ARCH_FEAT_SM103_ALL)
__device__ __forceinline__ void mma_tf32_ss(uint32_t d, uint64_t a, uint64_t b,
                                            uint32_t idesc, uint32_t en) {
    asm volatile(
        "{\n\t.reg .pred p;\n\tsetp.ne.u32 p, %4, 0;\n\t"
        "tcgen05.mma.cta_group::1.kind::tf32 [%0], %1, %2, %3, {%5, %5, %5, %5}, p;\n\t}\n"
        :: "r"(d), "l"(a), "l"(b), "r"(idesc), "r"(en), "r"(0u) : "memory");
}
#define MBAR_WAIT_PARITY(addr, ph) do {                                          \
    uint32_t _m = (addr), _p = (ph), _done;                                      \
    asm volatile("{\n\t.reg .pred p;\n\t"                                        \
        "mbarrier.try_wait.parity.acquire.cta.shared::cta.b64 p, [%1], %2;\n\t"  \
        "selp.b32 %0, 1, 0, p;\n\t}" : "=r"(_done) : "r"(_m), "r"(_p) : "memory");\
    if (!_done) {                                                                \
        asm volatile("{\n\t.reg .pred P1;\n\t"                                   \
            "WL_%=:\n\t"                                                         \
            "mbarrier.try_wait.parity.acquire.cta.shared::cta.b64 P1, [%0], %1, 0x989680;\n\t" \
            "@P1 bra.uni WD_%=;\n\tbra.uni WL_%=;\n\tWD_%=:\n\t}"                \
            :: "r"(_m), "r"(_p) : "memory");                                     \
    } } while (0)
#define LDTM_X16(r, addr)                                                        \
    asm volatile("tcgen05.ld.sync.aligned.32x32b.x16.b32 "                       \
        "{%0, %1, %2, %3, %4, %5, %6, %7, %8, %9, %10, %11, %12, %13, %14, %15}, [%16];" \
        : "=r"((r)[0]),  "=r"((r)[1]),  "=r"((r)[2]),  "=r"((r)[3]),             \
          "=r"((r)[4]),  "=r"((r)[5]),  "=r"((r)[6]),  "=r"((r)[7]),             \
          "=r"((r)[8]),  "=r"((r)[9]),  "=r"((r)[10]), "=r"((r)[11]),            \
          "=r"((r)[12]), "=r"((r)[13]), "=r"((r)[14]), "=r"((r)[15])             \
        : "r"(addr))
#define IDESC_TF32 0x08100910u
#define DESC_BASE ((2ull << 61) | (1ull << 46) | (64ull << 32) | (1ull << 16))
__device__ __forceinline__ uint64_t mk_desc(uint32_t addr) {
    return DESC_BASE | ((uint64_t)(addr >> 4) & 0x3FFF);
}
#endif

// decoder dynamic smem layout (from 1024-aligned base)
#define OFF_B     0          // 4 x 16384 = 65536 (W2T, SW128)
#define OFF_A     65536      // 4 x 32768 = 131072 (h1 tiles, SW128)
#define DEC_DYN   (65536 + 131072 + 1024)

// node-MLP kernel dynamic smem layout (float indices)
#define NOFF_W1   0            // 80*64
#define NOFF_W2   5120         // 64*64
#define NOFF_W3   9216         // 64*16
#define NOFF_B    10240        // 64+64+16 = 144
#define NOFF_AUG  10384        // 32*80
#define NOFF_H1   12944        // 32*64
#define NOFF_H2   14992        // 32*64
#define NODE_DYN  ((14992 + 2048) * 4)

// ---------------------------------------------------------------------------
__global__ void w2t_kernel(const float* __restrict__ W2) {
    int idx = blockIdx.x * 256 + threadIdx.x;
    if (idx < KT * MOUT * MHID) {
        int k = idx >> 12, rem = idx & 4095, kk = rem >> 6, m = rem & 63;
        uint32_t v = f2tf32(W2[(k * MHID + kk) * MOUT + m]);
        ((uint32_t*)g_W2T)[(k * MOUT + m) * MHID + kk] = v;
    }
}

// ---------------------------------------------------------------------------
__global__ __launch_bounds__(256) void uv_kernel(
    const float* __restrict__ inp, const float* __restrict__ W1,
    const float* __restrict__ b1)
{
    const int n = blockIdx.x, b = blockIdx.y;
    const int t = threadIdx.x;
    const int k = t >> 6, h = t & 63;
    __shared__ float xs[NIN];
    if (t < NIN) xs[t] = inp[(b * NIN + t) * NN + n];
    __syncthreads();
    const float* w = W1 + k * (2 * NIN) * MHID;
    float u = 0.f, v = b1[k * MHID + h];
#pragma unroll
    for (int f = 0; f < NIN; f++) {
        u = fmaf(xs[f], w[f * MHID + h], u);
        v = fmaf(xs[f], w[(NIN + f) * MHID + h], v);
    }
    g_U[((b * NN + n) * KT + k) * MHID + h] = u;
    g_V[((b * NN + n) * KT + k) * MHID + h] = v;
}

// ---------------------------------------------------------------------------
// Persistent edge-GEMM decoder: grid = 148, 512 threads, 1 CTA/SM.
// Produces g_AGG[b][i][m]; node MLP is a separate kernel.
// ---------------------------------------------------------------------------
__global__ __launch_bounds__(512, 1) void decoder_kernel(
    const float* __restrict__ rel_types, const float* __restrict__ W2,
    const float* __restrict__ b2)
{
    extern __shared__ char dsm[];
    __shared__ float rts[2][NN][KT];
    __shared__ __align__(16) float vs[KT][MHID];
    __shared__ float b2s[KT][MOUT];
    __shared__ float pbuf[16][16];
    __shared__ uint32_t tmem_ptr_s;
    __shared__ __align__(8) uint64_t mbar;

    const int t = threadIdx.x;
    const int wid = t >> 5, lane = t & 31;

    const uint32_t dyn = smem_u32(dsm);
    const uint32_t base = (dyn + 1023) & ~1023u;
    char* P = dsm + (base - dyn);

    if (t < 256) b2s[t >> 6][t & 63] = b2[t];

#if defined(__CUDA_ARCH_FEAT_SM103_ALL)
    const uint32_t mb = smem_u32(&mbar);

    // stage all 4 B tiles (W2T, SW128 blocked-atom) once
    for (int idx = t; idx < KT * 64 * 16; idx += 512) {
        const int k = idx >> 10, n = (idx >> 4) & 63, c = (idx & 15) * 4;
        uint4 w4 = *(const uint4*)((const uint32_t*)g_W2T + (k * MOUT + n) * MHID + c);
        uint32_t byte = ((n >> 3) + (c >> 5) * 8) * 1024 + (n & 7) * 128 + (c & 31) * 4;
        byte ^= (byte >> 3) & 0x70;
        *(uint4*)(P + OFF_B + k * 16384 + byte) = w4;
    }
    if (t == 0)
        asm volatile("mbarrier.init.shared.b64 [%0], 1;" :: "r"(mb) : "memory");
    if (wid == 0) {
        asm volatile("tcgen05.alloc.cta_group::1.sync.aligned.shared::cta.b32 [%0], %1;"
                     :: "r"(smem_u32(&tmem_ptr_s)), "r"(512u) : "memory");
        asm volatile("tcgen05.relinquish_alloc_permit.cta_group::1.sync.aligned;");
    }
    __syncthreads();
    const uint32_t tmem = tmem_ptr_s;

    const int colbase = (wid >> 2) * 16;      // {0,16,32,48}
    const int jrow = (wid & 3) * 32 + lane;   // 0..127

    int ph = 0;          // mbar wait parity
    int tcount = 0;      // local tile counter
    int pb = 0, pi = 0, pq = 0, prb = 0;

    // epilogue for tile (pb,pi): TMEM banks pq*4.., rel_types buffer prb
    auto do_epilogue = [&](int eb, int ei, int eq, int erb) {
        const float rt0 = rts[erb][jrow][0];
        const float rt1 = rts[erb][jrow][1];
        const float rt2 = rts[erb][jrow][2];
        const float rt3 = rts[erb][jrow][3];
        float acc[16];
        {
            uint32_t da[16], db[16];
            LDTM_X16(da, tmem + (eq * 4 + 0) * 64 + colbase);
            LDTM_X16(db, tmem + (eq * 4 + 1) * 64 + colbase);
            asm volatile("tcgen05.wait::ld.sync.aligned;" ::: "memory");
#pragma unroll
            for (int c = 0; c < 16; c++) {
                const float v0 = fmaxf(__uint_as_float(da[c]) + b2s[0][colbase + c], 0.f);
                const float v1 = fmaxf(__uint_as_float(db[c]) + b2s[1][colbase + c], 0.f);
                acc[c] = rt0 * v0 + rt1 * v1;
            }
            LDTM_X16(da, tmem + (eq * 4 + 2) * 64 + colbase);
            LDTM_X16(db, tmem + (eq * 4 + 3) * 64 + colbase);
            asm volatile("tcgen05.wait::ld.sync.aligned;" ::: "memory");
#pragma unroll
            for (int c = 0; c < 16; c++) {
                const float v2 = fmaxf(__uint_as_float(da[c]) + b2s[2][colbase + c], 0.f);
                const float v3 = fmaxf(__uint_as_float(db[c]) + b2s[3][colbase + c], 0.f);
                acc[c] = fmaf(rt2, v2, acc[c]);
                acc[c] = fmaf(rt3, v3, acc[c]);
            }
        }
        asm volatile("tcgen05.fence::before_thread_sync;" ::: "memory");
        // butterfly reduce over 32 lanes (sum over this lane-group's j rows)
#pragma unroll
        for (int o = 16; o >= 1; o >>= 1)
#pragma unroll
            for (int c = 0; c < 16; c++)
                acc[c] += __shfl_xor_sync(0xFFFFFFFFu, acc[c], o);
        if (lane == 0)
#pragma unroll
            for (int c = 0; c < 16; c++) pbuf[wid][c] = acc[c];
        __syncthreads();
        if (t < 64) {
            const int cg = t >> 4, cm = t & 15;
            const float s = pbuf[cg * 4 + 0][cm] + pbuf[cg * 4 + 1][cm] +
                            pbuf[cg * 4 + 2][cm] + pbuf[cg * 4 + 3][cm];
            g_AGG[(eb * NN + ei) * MOUT + t] = s;
        }
    };

    for (int tile = blockIdx.x; tile < BB * NN; tile += gridDim.x) {
        const int b = tile >> 7, i = tile & 127;
        const int rb = tcount & 1, q = tcount & 1;

        // stage per-tile constants (other buffer than epilogue(T-1) uses)
        if (t < 256) vs[t >> 6][t & 63] = g_V[((b * NN + i) * KT) * MHID + t];
        {
            const float* rtp = rel_types + (size_t)(b * EDGES + i * (NN - 1)) * KT;
            for (int idx = t; idx < (NN - 1) * KT; idx += 512)
                rts[rb][idx >> 2][idx & 3] = rtp[idx];
            if (t < KT) rts[rb][NN - 1][t] = 0.f;
        }
        // A smem & the TMEM bank-set q are free once MMA(T-1) completed
        if (tcount > 0) { MBAR_WAIT_PARITY(mb, ph); ph ^= 1; }
        __syncthreads();

        // ---- build ALL 4 A tiles in one pass ----
        for (int idx = t; idx < 128 * KT * 16; idx += 512) {
            const int r = idx >> 6, k = (idx >> 4) & 3, c = (idx & 15) * 4;
            uint4 w4 = make_uint4(0u, 0u, 0u, 0u);
            if (r < NN - 1) {
                const int j = r + (r >= i);
                const float4 u = *(const float4*)(g_U + ((b * NN + j) * KT + k) * MHID + c);
                const float4 vv = *(const float4*)&vs[k][c];
                w4.x = f2tf32(fmaxf(u.x + vv.x, 0.f));
                w4.y = f2tf32(fmaxf(u.y + vv.y, 0.f));
                w4.z = f2tf32(fmaxf(u.z + vv.z, 0.f));
                w4.w = f2tf32(fmaxf(u.w + vv.w, 0.f));
            }
            uint32_t byte = ((r >> 3) + (c >> 5) * 16) * 1024 + (r & 7) * 128 + (c & 31) * 4;
            byte ^= (byte >> 3) & 0x70;
            *(uint4*)(P + OFF_A + k * 32768 + byte) = w4;
        }
        __syncthreads();

        // ---- issue all 4 GEMMs (32 dispatches) + single commit ----
        if (t == 0) {
            asm volatile("fence.proxy.async.shared::cta;" ::: "memory");
#pragma unroll
            for (int k = 0; k < KT; k++) {
                const uint64_t ad = mk_desc(base + OFF_A + k * 32768);
                const uint64_t bd = mk_desc(base + OFF_B + k * 16384);
                const uint32_t dcol = tmem + (q * 4 + k) * 64;
#pragma unroll
                for (int s = 0; s < 8; s++)
                    mma_tf32_ss(dcol,
                                ad + ((s >> 2) ? 1024u : 0u) + (s & 3) * 2,
                                bd + ((s >> 2) ? 512u : 0u) + (s & 3) * 2,
                                IDESC_TF32, (uint32_t)(s > 0));
            }
            asm volatile(
                "tcgen05.commit.cta_group::1.mbarrier::arrive::one.shared::cluster.b64 [%0];"
                :: "r"(mb) : "memory");
        }
        asm volatile("tcgen05.fence::after_thread_sync;" ::: "memory");

        // ---- epilogue for the previous tile (overlaps MMA(T)) ----
        if (tcount > 0) do_epilogue(pb, pi, pq, prb);

        pb = b; pi = i; pq = q; prb = rb;
        tcount++;
    }
    if (tcount > 0) {
        MBAR_WAIT_PARITY(mb, ph); ph ^= 1;
        asm volatile("tcgen05.fence::after_thread_sync;" ::: "memory");
        do_epilogue(pb, pi, pq, prb);
    }

    __syncthreads();
    if (t == 0)
        asm volatile("mbarrier.inval.shared.b64 [%0];" :: "r"(mb) : "memory");
    if (wid == 0)
        asm volatile("tcgen05.dealloc.cta_group::1.sync.aligned.b32 %0, %1;"
                     :: "r"(tmem), "r"(512u));
#else
    // ============ SIMT fallback (compile-only for plain sm_103) ============
    float* h1  = (float*)P;                  // [128][68]
    float* W2s = (float*)(P + 128 * 68 * 4); // [64][64]
    __shared__ float pb2[16][17];

    for (int tile = blockIdx.x; tile < BB * NN; tile += gridDim.x) {
        const int b = tile >> 7, i = tile & 127;
        __syncthreads();
        if (t < 256) vs[t >> 6][t & 63] = g_V[((b * NN + i) * KT) * MHID + t];
        {
            const float* rtp = rel_types + (size_t)(b * EDGES + i * (NN - 1)) * KT;
            for (int idx = t; idx < (NN - 1) * KT; idx += 512)
                rts[0][idx >> 2][idx & 3] = rtp[idx];
            if (t < KT) rts[0][NN - 1][t] = 0.f;
        }

        const int r = t >> 2, cq = (t & 3) * 16;
        float aggv[16];
#pragma unroll
        for (int c = 0; c < 16; c++) aggv[c] = 0.f;

        for (int k = 0; k < KT; k++) {
            __syncthreads();
            for (int idx = t; idx < 128 * 64; idx += 512) {
                const int rr = idx >> 6, h = idx & 63;
                float val = 0.f;
                if (rr < NN - 1) {
                    const int j = rr + (rr >= i);
                    val = fmaxf(g_U[((b * NN + j) * KT + k) * MHID + h] + vs[k][h], 0.f);
                }
                h1[rr * 68 + h] = val;
            }
            for (int idx = t; idx < 64 * 64; idx += 512)
                W2s[idx] = W2[k * 64 * 64 + idx];
            __syncthreads();

            float acc[16];
#pragma unroll
            for (int c = 0; c < 16; c++) acc[c] = 0.f;
            for (int kk = 0; kk < 64; kk++) {
                const float a = h1[r * 68 + kk];
#pragma unroll
                for (int c = 0; c < 16; c++)
                    acc[c] = fmaf(a, W2s[kk * 64 + cq + c], acc[c]);
            }
            const float rt = rts[0][r][k];
#pragma unroll
            for (int c = 0; c < 16; c++)
                aggv[c] = fmaf(rt, fmaxf(acc[c] + b2s[k][cq + c], 0.f), aggv[c]);
        }

        // reduce over j: lanes of 4 threads share (r group) — use butterfly over 128 rows
        __syncthreads();
        float* red = (float*)P;  // [64 m][stride 132]
#pragma unroll
        for (int c = 0; c < 16; c++) red[(cq + c) * 132 + r] = aggv[c];
        __syncthreads();
        if (t < 64) {
            float s = 0.f;
            for (int l = 0; l < 128; l++) s += red[t * 132 + l];
            g_AGG[(b * NN + i) * MOUT + t] = s;
        }
        __syncthreads();
    }
#endif
}

// ---------------------------------------------------------------------------
// Node MLP: grid = 128 (4 CTAs per batch, 32 nodes each), 256 threads.
// ---------------------------------------------------------------------------
__global__ __launch_bounds__(256) void node_kernel(
    const float* __restrict__ inp,
    const float* __restrict__ Wo1, const float* __restrict__ bo1,
    const float* __restrict__ Wo2, const float* __restrict__ bo2,
    const float* __restrict__ Wo3, const float* __restrict__ bo3,
    float* __restrict__ out)
{
    extern __shared__ float nsm[];
    float* sW1 = nsm + NOFF_W1;
    float* sW2 = nsm + NOFF_W2;
    float* sW3 = nsm + NOFF_W3;
    float* sB  = nsm + NOFF_B;
    float* aug = nsm + NOFF_AUG;   // [32][80]
    float* h1  = nsm + NOFF_H1;    // [32][64]
    float* h2  = nsm + NOFF_H2;    // [32][64]

    const int t = threadIdx.x;
    const int b = blockIdx.x >> 2, n0 = (blockIdx.x & 3) * 32;

    for (int idx = t; idx < 80 * 64; idx += 256) sW1[idx] = Wo1[idx];
    for (int idx = t; idx < 64 * 64; idx += 256) sW2[idx] = Wo2[idx];
    for (int idx = t; idx < 64 * 16; idx += 256) sW3[idx] = Wo3[idx];
    if (t < 64) sB[t] = bo1[t];
    if (t < 64) sB[64 + t] = bo2[t];
    if (t < 16) sB[128 + t] = bo3[t];

    for (int idx = t; idx < 32 * 80; idx += 256) {
        const int nn = idx / 80, f = idx % 80;
        aug[nn * 80 + f] = (f < NIN)
            ? inp[(b * NIN + f) * NN + (n0 + nn)]
            : g_AGG[(b * NN + n0 + nn) * MOUT + (f - NIN)];
    }
    __syncthreads();

    const int nn = t >> 3, hb = (t & 7) * 8;
    {
        float s[8];
#pragma unroll
        for (int x = 0; x < 8; x++) s[x] = sB[hb + x];
        for (int f = 0; f < NIN + MOUT; f++) {
            const float a = aug[nn * 80 + f];
#pragma unroll
            for (int x = 0; x < 8; x++) s[x] = fmaf(a, sW1[f * 64 + hb + x], s[x]);
        }
#pragma unroll
        for (int x = 0; x < 8; x++) h1[nn * 64 + hb + x] = fmaxf(s[x], 0.f);
    }
    __syncthreads();
    {
        float s[8];
#pragma unroll
        for (int x = 0; x < 8; x++) s[x] = sB[64 + hb + x];
        for (int f = 0; f < NHID; f++) {
            const float a = h1[nn * 64 + f];
#pragma unroll
            for (int x = 0; x < 8; x++) s[x] = fmaf(a, sW2[f * 64 + hb + x], s[x]);
        }
#pragma unroll
        for (int x = 0; x < 8; x++) h2[nn * 64 + hb + x] = fmaxf(s[x], 0.f);
    }
    __syncthreads();
    {
        const int o = (t & 7) * 2;
        float s0 = sB[128 + o], s1 = sB[128 + o + 1];
        for (int h = 0; h < NHID; h++) {
            const float a = h2[nn * 64 + h];
            s0 = fmaf(a, sW3[h * 16 + o], s0);
            s1 = fmaf(a, sW3[h * 16 + o + 1], s1);
        }
        out[(b * NOUT + o) * NN + (n0 + nn)] = s0;
        out[(b * NOUT + o + 1) * NN + (n0 + nn)] = s1;
    }
}

// ---------------------------------------------------------------------------
extern "C" void kernel_launch(void* const* d_in, const int* in_sizes, int n_in,
                              void* d_out, int out_size)
{
    const float* inp       = (const float*)d_in[0];
    const float* rel_types = (const float*)d_in[3];
    const float* W1  = (const float*)d_in[4];
    const float* b1  = (const float*)d_in[5];
    const float* W2  = (const float*)d_in[6];
    const float* b2  = (const float*)d_in[7];
    const float* Wo1 = (const float*)d_in[8];
    const float* bo1 = (const float*)d_in[9];
    const float* Wo2 = (const float*)d_in[10];
    const float* bo2 = (const float*)d_in[11];
    const float* Wo3 = (const float*)d_in[12];
    const float* bo3 = (const float*)d_in[13];
    float* out = (float*)d_out;

    (void)cudaFuncSetAttribute(decoder_kernel,
                               cudaFuncAttributeMaxDynamicSharedMemorySize, DEC_DYN);
    (void)cudaFuncSetAttribute(node_kernel,
                               cudaFuncAttributeMaxDynamicSharedMemorySize, NODE_DYN);

    w2t_kernel<<<64, 256>>>(W2);
    uv_kernel<<<dim3(NN, BB), 256>>>(inp, W1, b1);
    decoder_kernel<<<148, 512, DEC_DYN>>>(rel_types, W2, b2);
    node_kernel<<<128, 256, NODE_DYN>>>(inp, Wo1, bo1, Wo2, bo2, Wo3, bo3, out);
}